// round 4
// baseline (speedup 1.0000x reference)
#include <cuda_runtime.h>
#include <cuda_bf16.h>
#include <math.h>

#define BB 64
#define TT 1024
#define MAXLAG 256
#define LAGS_PER_BLOCK 64
#define THREADS1 512

// Scratch for per-(batch,lag) sum of squared displacements.
__device__ float g_S[BB * MAXLAG];

// Phase 1: S[b,l] = sum_{p=0}^{npos-1} |traj[b,p+l] - traj[b,p]|^2
// grid = (B, MAXLAG/LAGS_PER_BLOCK), block = 512 threads (16 warps, 4 lags each)
__global__ __launch_bounds__(THREADS1) void msd_kernel(
    const float* __restrict__ traj,
    const int* __restrict__ lengths)
{
    __shared__ float2 s[TT];
    const int b = blockIdx.x;
    const float2* tr = reinterpret_cast<const float2*>(traj) + (size_t)b * TT;
    for (int i = threadIdx.x; i < TT; i += THREADS1) s[i] = tr[i];
    __syncthreads();

    const int L = lengths[b];
    const int warp = threadIdx.x >> 5;
    const int lane = threadIdx.x & 31;

#pragma unroll
    for (int j = 0; j < LAGS_PER_BLOCK / 16; j++) {
        const int il = blockIdx.y * LAGS_PER_BLOCK + j * 16 + warp; // 0..255
        const int lag = il + 1;
        int npos = L - lag;
        if (npos > TT - 1) npos = TT - 1;
        if (npos < 0) npos = 0;

        float acc = 0.f;
        for (int p = lane; p < npos; p += 32) {
            const float2 a = s[p];
            const float2 e = s[p + lag];
            const float dx = e.x - a.x;
            const float dy = e.y - a.y;
            acc = fmaf(dx, dx, acc);
            acc = fmaf(dy, dy, acc);
        }
#pragma unroll
        for (int o = 16; o; o >>= 1) acc += __shfl_xor_sync(0xffffffffu, acc, o);
        if (lane == 0) g_S[b * MAXLAG + il] = acc;
    }
}

// Phase 2: log-log linear fit residual loss. 1 block, 256 threads.
// 8 warps, each warp fully owns 8 batches (in-warp reductions only).
__global__ __launch_bounds__(256) void loss_kernel(
    const float* __restrict__ alpha_pred,
    const int* __restrict__ lengths,
    float* __restrict__ out)
{
    __shared__ float warp_acc[8];
    const int warp = threadIdx.x >> 5;
    const int lane = threadIdx.x & 31;

    float logl[8];
#pragma unroll
    for (int j = 0; j < 8; j++) logl[j] = logf((float)(lane + 32 * j + 1));

    float acc = 0.f;
    for (int b = warp; b < BB; b += 8) {
        const int L = lengths[b];
        const float alpha = alpha_pred[b];
        float resid[8], mask[8];
        float sr = 0.f, sm = 0.f;
#pragma unroll
        for (int j = 0; j < 8; j++) {
            const int il = lane + 32 * j;
            const int lag = il + 1;
            int npos = L - lag;
            if (npos > TT - 1) npos = TT - 1;
            const int cnt = (npos > 0) ? npos : 1;           // counts = max(#valid, 1)
            const float S = g_S[b * MAXLAG + il];
            const float msd = S / (float)cnt;
            const float lm = logf(msd + 1e-8f);
            const float m = (L > lag) ? 1.f : 0.f;
            resid[j] = lm - alpha * logl[j];
            mask[j] = m;
            sr += resid[j] * m;
            sm += m;
        }
#pragma unroll
        for (int o = 16; o; o >>= 1) {
            sr += __shfl_xor_sync(0xffffffffu, sr, o);
            sm += __shfl_xor_sync(0xffffffffu, sm, o);
        }
        const float denom = (sm > 1.f) ? sm : 1.f;
        const float intercept = sr / denom;
        float se = 0.f;
#pragma unroll
        for (int j = 0; j < 8; j++) {
            const float d = intercept - resid[j];   // == alpha*logl + intercept - log_msd
            se += d * d * mask[j];
        }
#pragma unroll
        for (int o = 16; o; o >>= 1) se += __shfl_xor_sync(0xffffffffu, se, o);
        acc += se / denom;
    }

    if (lane == 0) warp_acc[warp] = acc;
    __syncthreads();
    if (threadIdx.x == 0) {
        float t = 0.f;
#pragma unroll
        for (int w = 0; w < 8; w++) t += warp_acc[w];
        out[0] = t / (float)BB;
    }
}

extern "C" void kernel_launch(void* const* d_in, const int* in_sizes, int n_in,
                              void* d_out, int out_size)
{
    const float* alpha_pred   = (const float*)d_in[0];
    const float* trajectory   = (const float*)d_in[1];
    const int*   lengths      = (const int*)d_in[2];
    float* out = (float*)d_out;

    dim3 g1(BB, MAXLAG / LAGS_PER_BLOCK, 1);
    msd_kernel<<<g1, THREADS1>>>(trajectory, lengths);
    loss_kernel<<<1, 256>>>(alpha_pred, lengths, out);
}

// round 5
// speedup vs baseline: 3.0086x; 3.0086x over previous
#include <cuda_runtime.h>
#include <cuda_bf16.h>
#include <math.h>

#define BB 64
#define TT 1024
#define MAXLAG 256
#define THREADS1 512

// Scratch (device globals — no allocation allowed).
__device__ float g_S[BB * MAXLAG];   // per-(batch,lag) sum of squared displacements
__device__ float g_P[BB];            // per-batch loss
__device__ int   g_done = 0;         // finalize counter (self-resetting)

// Phase 1: S[b,l] = sum_{p=0}^{npos-1} |traj[b,p+l] - traj[b,p]|^2
// grid = (64, 4), block = 512 (16 warps). Warp w of block (b,y) owns lags
// il = y*64 + 16j + w (j=0..3), reusing the start point s[p] across its 4 lags.
__global__ __launch_bounds__(THREADS1) void msd_kernel(
    const float* __restrict__ traj,
    const int* __restrict__ lengths)
{
    __shared__ float2 s[TT];
    const int b = blockIdx.x;
    const int y = blockIdx.y;
    const float2* tr = reinterpret_cast<const float2*>(traj) + (size_t)b * TT;
    for (int i = threadIdx.x; i < TT; i += THREADS1) s[i] = tr[i];
    __syncthreads();

    const int L    = lengths[b];
    const int w    = threadIdx.x >> 5;
    const int lane = threadIdx.x & 31;

    const int lag0 = y * 64 + w + 1;       // j adds 16 per step; lag_j = lag0 + 16j
    // npos_j = L - lag_j  (always <= T-1 = 1023 since lag >= 1, L <= T)
    int np0 = L - lag0;           if (np0 < 0) np0 = 0;
    int np1 = np0 - 16;           if (np1 < 0) np1 = 0;
    int np2 = np0 - 32;           if (np2 < 0) np2 = 0;
    int np3 = np0 - 48;           if (np3 < 0) np3 = 0;

    float acc0 = 0.f, acc1 = 0.f, acc2 = 0.f, acc3 = 0.f;

    for (int p = lane; p < np0; p += 32) {
        const float2 a = s[p];
        {
            const float2 e = s[p + lag0];            // p+lag0 <= L-1 in-bounds
            const float dx = e.x - a.x, dy = e.y - a.y;
            acc0 = fmaf(dx, dx, acc0); acc0 = fmaf(dy, dy, acc0);
        }
        if (p < np1) {
            const float2 e = s[p + lag0 + 16];       // <= L-1 when p < np1
            const float dx = e.x - a.x, dy = e.y - a.y;
            acc1 = fmaf(dx, dx, acc1); acc1 = fmaf(dy, dy, acc1);
        }
        if (p < np2) {
            const float2 e = s[p + lag0 + 32];
            const float dx = e.x - a.x, dy = e.y - a.y;
            acc2 = fmaf(dx, dx, acc2); acc2 = fmaf(dy, dy, acc2);
        }
        if (p < np3) {
            const float2 e = s[p + lag0 + 48];
            const float dx = e.x - a.x, dy = e.y - a.y;
            acc3 = fmaf(dx, dx, acc3); acc3 = fmaf(dy, dy, acc3);
        }
    }

#pragma unroll
    for (int o = 16; o; o >>= 1) {
        acc0 += __shfl_xor_sync(0xffffffffu, acc0, o);
        acc1 += __shfl_xor_sync(0xffffffffu, acc1, o);
        acc2 += __shfl_xor_sync(0xffffffffu, acc2, o);
        acc3 += __shfl_xor_sync(0xffffffffu, acc3, o);
    }
    if (lane == 0) {
        float* dst = &g_S[b * MAXLAG + y * 64 + w];
        dst[0]  = acc0;
        dst[16] = acc1;
        dst[32] = acc2;
        dst[48] = acc3;
    }
}

// Phase 2: per-batch log-log fit. grid = 64 blocks (1 per batch), 256 threads
// (1 per lag). Last block to finish reduces g_P -> out (deterministic order).
__global__ __launch_bounds__(256) void fit_kernel(
    const float* __restrict__ alpha_pred,
    const int* __restrict__ lengths,
    float* __restrict__ out)
{
    __shared__ float sh[16];
    const int b    = blockIdx.x;
    const int il   = threadIdx.x;
    const int lag  = il + 1;
    const int w    = threadIdx.x >> 5;
    const int lane = threadIdx.x & 31;

    const int   L     = lengths[b];
    const float alpha = alpha_pred[b];

    int np  = L - lag;
    const int cnt = (np > 0) ? np : 1;               // counts = max(#valid, 1)
    const float S   = g_S[b * MAXLAG + il];
    const float lm  = logf(S / (float)cnt + 1e-8f);
    const float ll  = logf((float)lag);
    const float m   = (L > lag) ? 1.f : 0.f;
    const float resid = lm - alpha * ll;

    // reduction 1: sum(resid*m), sum(m)
    float sr = resid * m, sm = m;
#pragma unroll
    for (int o = 16; o; o >>= 1) {
        sr += __shfl_xor_sync(0xffffffffu, sr, o);
        sm += __shfl_xor_sync(0xffffffffu, sm, o);
    }
    if (lane == 0) { sh[w] = sr; sh[8 + w] = sm; }
    __syncthreads();
    float srt = 0.f, smt = 0.f;
#pragma unroll
    for (int k = 0; k < 8; k++) { srt += sh[k]; smt += sh[8 + k]; }

    const float denom     = (smt > 1.f) ? smt : 1.f;
    const float intercept = srt / denom;

    // reduction 2: sum((intercept - resid)^2 * m)
    const float d  = intercept - resid;
    float se = d * d * m;
#pragma unroll
    for (int o = 16; o; o >>= 1) se += __shfl_xor_sync(0xffffffffu, se, o);
    __syncthreads();                 // protect sh reuse
    if (lane == 0) sh[w] = se;
    __syncthreads();

    if (threadIdx.x == 0) {
        float t = 0.f;
#pragma unroll
        for (int k = 0; k < 8; k++) t += sh[k];
        g_P[b] = t / denom;
        __threadfence();
        const int old = atomicAdd(&g_done, 1);
        if (old == BB - 1) {
            g_done = 0;              // reset for next graph replay
            __threadfence();
            const volatile float* vp = g_P;
            float tot = 0.f;
#pragma unroll
            for (int i = 0; i < BB; i++) tot += vp[i];
            out[0] = tot / (float)BB;
        }
    }
}

extern "C" void kernel_launch(void* const* d_in, const int* in_sizes, int n_in,
                              void* d_out, int out_size)
{
    const float* alpha_pred = (const float*)d_in[0];
    const float* trajectory = (const float*)d_in[1];
    const int*   lengths    = (const int*)d_in[2];
    float* out = (float*)d_out;

    dim3 g1(BB, 4, 1);
    msd_kernel<<<g1, THREADS1>>>(trajectory, lengths);
    fit_kernel<<<BB, 256>>>(alpha_pred, lengths, out);
}